// round 3
// baseline (speedup 1.0000x reference)
#include <cuda_runtime.h>

#define NN   50000
#define EE   800000
#define RR   8
#define DIN  64
#define DHID 128
#define DOUT 64
#define EPSF 1e-5f
#define NSEG (NN * RR)            // 400000
#define NB   ((NSEG + 255) / 256) // 1563 scan blocks

// ---------------- scratch (device globals; no allocation allowed) ----------------
__device__ float g_S1[NN * RR * DIN];   // [N,8,64] per-(dst,rel) MEANS of x[src]
__device__ int   g_cnt[NSEG];           // per-(dst,rel) edge counts
__device__ int   g_off[NSEG];           // exclusive prefix (CSR offsets)
__device__ int   g_cursor[NSEG];        // scatter cursors
__device__ float g_invcnt[NSEG];        // 1/cnt (0 if empty)
__device__ int   g_sorted[EE];          // src node id, sorted by seg
__device__ int   g_bsum[NB];            // scan block sums
__device__ int   g_bpre[NB];            // scan block prefixes
__device__ float g_h[NN * DHID];        // layer-1 output [N,128] (post-LN)
__device__ float g_C2[NN * 9 * DOUT];   // [N,9,64]: r<8 = h@W2[r]; r=8 = h@root2+bias2
__device__ int   g_is64;                // edge index dtype flag

// ---------------- helpers ----------------
__device__ __forceinline__ int ld_idx(const void* p, int i, int is64) {
    if (is64) return (int)(((const long long*)p)[i]);
    return ((const int*)p)[i];
}

__global__ void detect_kernel(const int* __restrict__ ei) {
    int all0 = 1;
    for (int k = 0; k < 32; k++)
        if (ei[2 * k + 1] != 0) all0 = 0;
    g_is64 = all0;
}

__global__ void zero_cnt_kernel() {
    int i = blockIdx.x * 256 + threadIdx.x;
    if (i < NSEG / 4) ((int4*)g_cnt)[i] = make_int4(0, 0, 0, 0);
}

__global__ void count_kernel(const void* __restrict__ ei, const void* __restrict__ et) {
    int e = blockIdx.x * 256 + threadIdx.x;
    if (e >= EE) return;
    int is64 = g_is64;
    int dst = ld_idx(ei, EE + e, is64);
    int r   = ld_idx(et, e, is64);
    atomicAdd(&g_cnt[dst * RR + r], 1);
}

// --- 3-phase exclusive scan over g_cnt -> g_off ---
__global__ void scan1_kernel() {
    __shared__ int sm[256];
    int b = blockIdx.x, t = threadIdx.x;
    int i = b * 256 + t;
    int v = (i < NSEG) ? g_cnt[i] : 0;
    sm[t] = v;
    __syncthreads();
    for (int o = 1; o < 256; o <<= 1) {
        int u = (t >= o) ? sm[t - o] : 0;
        __syncthreads();
        sm[t] += u;
        __syncthreads();
    }
    if (i < NSEG) g_off[i] = sm[t] - v;   // exclusive within block
    if (t == 255) g_bsum[b] = sm[255];
}

__global__ void scan2_kernel() {   // one block of 1024 threads scans NB block sums
    __shared__ int sm[1024];
    int t = threadIdx.x;
    int i0 = 2 * t, i1 = 2 * t + 1;
    int v0 = (i0 < NB) ? g_bsum[i0] : 0;
    int v1 = (i1 < NB) ? g_bsum[i1] : 0;
    int s = v0 + v1;
    sm[t] = s;
    __syncthreads();
    for (int o = 1; o < 1024; o <<= 1) {
        int u = (t >= o) ? sm[t - o] : 0;
        __syncthreads();
        sm[t] += u;
        __syncthreads();
    }
    int e = sm[t] - s;  // exclusive
    if (i0 < NB) g_bpre[i0] = e;
    if (i1 < NB) g_bpre[i1] = e + v0;
}

__global__ void scan3_kernel() {
    int i = blockIdx.x * 256 + threadIdx.x;
    if (i >= NSEG) return;
    int o = g_off[i] + g_bpre[blockIdx.x];
    g_off[i] = o;
    g_cursor[i] = o;
    int c = g_cnt[i];
    g_invcnt[i] = (c > 0) ? (1.0f / (float)c) : 0.0f;
}

__global__ void scatter_pos_kernel(const void* __restrict__ ei, const void* __restrict__ et) {
    int e = blockIdx.x * 256 + threadIdx.x;
    if (e >= EE) return;
    int is64 = g_is64;
    int src = ld_idx(ei, e, is64);
    int dst = ld_idx(ei, EE + e, is64);
    int r   = ld_idx(et, e, is64);
    int pos = atomicAdd(&g_cursor[dst * RR + r], 1);
    g_sorted[pos] = src;
}

// gather1: warp per dst node; S1[dst,r,:] = mean of x[src,:] over segment (dst,r).
__global__ void gather1_kernel(const float* __restrict__ x) {
    int w = blockIdx.x * 8 + (threadIdx.x >> 5);
    if (w >= NN) return;
    int lane = threadIdx.x & 31;
#pragma unroll
    for (int r = 0; r < RR; r++) {
        int seg = w * RR + r;
        int beg = g_off[seg];
        int cnt = g_cnt[seg];
        float inv = g_invcnt[seg];
        float sx = 0.f, sy = 0.f;
        for (int j = 0; j < cnt; j++) {
            int src = __ldg(&g_sorted[beg + j]);
            float2 v = __ldg((const float2*)(x + (size_t)src * DIN + lane * 2));
            sx += v.x; sy += v.y;
        }
        float2 o; o.x = sx * inv; o.y = sy * inv;
        *(float2*)(g_S1 + (size_t)w * 512 + r * 64 + lane * 2) = o;
    }
}

// GEMM1 + bias + LeakyReLU + LayerNorm fused:  h = LN(leaky([S1 | x] @ [W1 | root1] + bias1))
// A = [N, 576], B = [576, 128]. BM=128, BN=128, BK=16, 256 threads, 8x8 microtile.
__global__ __launch_bounds__(256) void gemm1_kernel(
    const float* __restrict__ x, const float* __restrict__ W1,
    const float* __restrict__ root1, const float* __restrict__ bias1,
    const float* __restrict__ gamma1, const float* __restrict__ beta1) {
    __shared__ float As[16][128];
    __shared__ float Bs[16][128];
    __shared__ float red[128][17];
    int n0 = blockIdx.x * 128;
    int tid = threadIdx.x;
    int tx = tid & 15, ty = tid >> 4;
    float acc[8][8];
#pragma unroll
    for (int i = 0; i < 8; i++)
#pragma unroll
        for (int j = 0; j < 8; j++) acc[i][j] = 0.f;

    for (int k0 = 0; k0 < 576; k0 += 16) {
#pragma unroll
        for (int p0 = 0; p0 < 2; p0++) {
            int p = tid + p0 * 256;           // 0..511
            int m = p >> 2, kq = p & 3;
            int n = n0 + m;
            float4 v = make_float4(0.f, 0.f, 0.f, 0.f);
            if (n < NN) {
                if (k0 < 512)
                    v = *(const float4*)(g_S1 + (size_t)n * 512 + k0 + kq * 4);
                else
                    v = *(const float4*)(x + (size_t)n * 64 + (k0 - 512) + kq * 4);
            }
            int kb = kq * 4;
            As[kb + 0][m] = v.x;
            As[kb + 1][m] = v.y;
            As[kb + 2][m] = v.z;
            As[kb + 3][m] = v.w;
        }
        const float* Bp = (k0 < 512) ? (W1 + (size_t)k0 * 128)
                                     : (root1 + (size_t)(k0 - 512) * 128);
#pragma unroll
        for (int p0 = 0; p0 < 2; p0++) {
            int p = tid + p0 * 256;
            int k = p >> 5, j4 = p & 31;
            *(float4*)&Bs[k][j4 * 4] = *(const float4*)(Bp + k * 128 + j4 * 4);
        }
        __syncthreads();
#pragma unroll
        for (int k = 0; k < 16; k++) {
            float a[8], b[8];
#pragma unroll
            for (int i = 0; i < 8; i++) a[i] = As[k][ty * 8 + i];
#pragma unroll
            for (int j = 0; j < 8; j++) b[j] = Bs[k][tx * 8 + j];
#pragma unroll
            for (int i = 0; i < 8; i++)
#pragma unroll
                for (int j = 0; j < 8; j++) acc[i][j] += a[i] * b[j];
        }
        __syncthreads();
    }

    // bias + leaky
#pragma unroll
    for (int i = 0; i < 8; i++)
#pragma unroll
        for (int j = 0; j < 8; j++) {
            float c = acc[i][j] + bias1[tx * 8 + j];
            acc[i][j] = (c >= 0.f) ? c : 0.2f * c;
        }

    // LN pass 1: row means (row = ty*8+i spans tx=0..15)
#pragma unroll
    for (int i = 0; i < 8; i++) {
        float ps = 0.f;
#pragma unroll
        for (int j = 0; j < 8; j++) ps += acc[i][j];
        red[ty * 8 + i][tx] = ps;
    }
    __syncthreads();
    float mu[8];
#pragma unroll
    for (int i = 0; i < 8; i++) {
        float s = 0.f;
#pragma unroll
        for (int t = 0; t < 16; t++) s += red[ty * 8 + i][t];
        mu[i] = s * (1.f / 128.f);
    }
    __syncthreads();
    // LN pass 2: centered sum of squares
#pragma unroll
    for (int i = 0; i < 8; i++) {
        float ps = 0.f;
#pragma unroll
        for (int j = 0; j < 8; j++) {
            float d = acc[i][j] - mu[i];
            ps += d * d;
        }
        red[ty * 8 + i][tx] = ps;
    }
    __syncthreads();
    float rstd[8];
#pragma unroll
    for (int i = 0; i < 8; i++) {
        float s = 0.f;
#pragma unroll
        for (int t = 0; t < 16; t++) s += red[ty * 8 + i][t];
        rstd[i] = rsqrtf(s * (1.f / 128.f) + EPSF);
    }

    float gm[8], bt[8];
#pragma unroll
    for (int j = 0; j < 8; j++) {
        gm[j] = gamma1[tx * 8 + j];
        bt[j] = beta1[tx * 8 + j];
    }
#pragma unroll
    for (int i = 0; i < 8; i++) {
        int n = n0 + ty * 8 + i;
        if (n >= NN) continue;
#pragma unroll
        for (int j = 0; j < 8; j++)
            g_h[(size_t)n * 128 + tx * 8 + j] = (acc[i][j] - mu[i]) * rstd[i] * gm[j] + bt[j];
    }
}

// GEMM2: C2[:, by, :] = h @ (by<8 ? W2[by] : root2) (+bias2 on by==8).
__global__ __launch_bounds__(256) void gemm2_kernel(
    const float* __restrict__ W2, const float* __restrict__ root2,
    const float* __restrict__ bias2) {
    __shared__ float As[16][128];
    __shared__ float Bs[16][64];
    int n0 = blockIdx.x * 128;
    int bx = blockIdx.y;  // 0..8
    const float* Bbase = (bx < 8) ? (W2 + (size_t)bx * DHID * DOUT) : root2;  // [128,64]
    int tid = threadIdx.x;
    int tx = tid & 15, ty = tid >> 4;
    float acc[8][4];
#pragma unroll
    for (int i = 0; i < 8; i++)
#pragma unroll
        for (int j = 0; j < 4; j++) acc[i][j] = 0.f;

    for (int k0 = 0; k0 < 128; k0 += 16) {
#pragma unroll
        for (int p0 = 0; p0 < 2; p0++) {
            int p = tid + p0 * 256;
            int m = p >> 2, kq = p & 3;
            int n = n0 + m;
            float4 v = make_float4(0.f, 0.f, 0.f, 0.f);
            if (n < NN) v = *(const float4*)(g_h + (size_t)n * 128 + k0 + kq * 4);
            int kb = kq * 4;
            As[kb + 0][m] = v.x; As[kb + 1][m] = v.y;
            As[kb + 2][m] = v.z; As[kb + 3][m] = v.w;
        }
        {
            int k = tid >> 4, j4 = tid & 15;
            *(float4*)&Bs[k][j4 * 4] = *(const float4*)(Bbase + (size_t)(k0 + k) * 64 + j4 * 4);
        }
        __syncthreads();
#pragma unroll
        for (int k = 0; k < 16; k++) {
            float a[8], b[4];
#pragma unroll
            for (int i = 0; i < 8; i++) a[i] = As[k][ty * 8 + i];
#pragma unroll
            for (int j = 0; j < 4; j++) b[j] = Bs[k][tx * 4 + j];
#pragma unroll
            for (int i = 0; i < 8; i++)
#pragma unroll
                for (int j = 0; j < 4; j++) acc[i][j] += a[i] * b[j];
        }
        __syncthreads();
    }
#pragma unroll
    for (int i = 0; i < 8; i++) {
        int n = n0 + ty * 8 + i;
        if (n >= NN) continue;
#pragma unroll
        for (int j = 0; j < 4; j++) {
            int jj = tx * 4 + j;
            float c = acc[i][j];
            if (bx == 8) c += bias2[jj];
            g_C2[(size_t)n * 576 + bx * 64 + jj] = c;
        }
    }
}

// gather2 + final LayerNorm fused: warp per dst.
// out[dst] = LN( C2[dst,8,:] + sum_r invcnt[dst,r] * sum_{e in seg} C2[src,r,:] )
__global__ void gather2_kernel(const float* __restrict__ gamma, const float* __restrict__ beta,
                               float* __restrict__ out) {
    int w = blockIdx.x * 8 + (threadIdx.x >> 5);
    if (w >= NN) return;
    int lane = threadIdx.x & 31;
    float2 acc = *(const float2*)(g_C2 + (size_t)w * 576 + 512 + lane * 2);
#pragma unroll
    for (int r = 0; r < RR; r++) {
        int seg = w * RR + r;
        int cnt = g_cnt[seg];
        if (cnt == 0) continue;
        int beg = g_off[seg];
        float inv = g_invcnt[seg];
        float sx = 0.f, sy = 0.f;
        for (int j = 0; j < cnt; j++) {
            int src = __ldg(&g_sorted[beg + j]);
            float2 v = __ldg((const float2*)(g_C2 + (size_t)src * 576 + r * 64 + lane * 2));
            sx += v.x; sy += v.y;
        }
        acc.x += sx * inv;
        acc.y += sy * inv;
    }
    // LayerNorm over 64 (2 values per lane)
    float s = acc.x + acc.y;
#pragma unroll
    for (int o = 16; o; o >>= 1) s += __shfl_xor_sync(0xFFFFFFFFu, s, o);
    float mu = s * (1.f / 64.f);
    float dx = acc.x - mu, dy = acc.y - mu;
    float sq = dx * dx + dy * dy;
#pragma unroll
    for (int o = 16; o; o >>= 1) sq += __shfl_xor_sync(0xFFFFFFFFu, sq, o);
    float rstd = rsqrtf(sq * (1.f / 64.f) + EPSF);
    float2 g = ((const float2*)gamma)[lane];
    float2 b = ((const float2*)beta)[lane];
    float2 o2;
    o2.x = dx * rstd * g.x + b.x;
    o2.y = dy * rstd * g.y + b.y;
    ((float2*)out)[(size_t)w * 32 + lane] = o2;
}

// ---------------- launch ----------------
extern "C" void kernel_launch(void* const* d_in, const int* in_sizes, int n_in,
                              void* d_out, int out_size) {
    const float* x      = (const float*)d_in[0];
    const void*  ei     = d_in[1];
    const void*  et     = d_in[2];
    const float* W1     = (const float*)d_in[3];
    const float* root1  = (const float*)d_in[4];
    const float* bias1  = (const float*)d_in[5];
    const float* gamma1 = (const float*)d_in[6];
    const float* beta1  = (const float*)d_in[7];
    const float* W2     = (const float*)d_in[8];
    const float* root2  = (const float*)d_in[9];
    const float* bias2  = (const float*)d_in[10];
    const float* gamma2 = (const float*)d_in[11];
    const float* beta2  = (const float*)d_in[12];
    float* out = (float*)d_out;

    detect_kernel<<<1, 1>>>((const int*)ei);
    zero_cnt_kernel<<<(NSEG / 4 + 255) / 256, 256>>>();
    count_kernel<<<(EE + 255) / 256, 256>>>(ei, et);
    scan1_kernel<<<NB, 256>>>();
    scan2_kernel<<<1, 1024>>>();
    scan3_kernel<<<NB, 256>>>();
    scatter_pos_kernel<<<(EE + 255) / 256, 256>>>(ei, et);
    gather1_kernel<<<(NN + 7) / 8, 256>>>(x);
    gemm1_kernel<<<(NN + 127) / 128, 256>>>(x, W1, root1, bias1, gamma1, beta1);
    gemm2_kernel<<<dim3((NN + 127) / 128, 9), 256>>>(W2, root2, bias2);
    gather2_kernel<<<(NN + 7) / 8, 256>>>(gamma2, beta2, out);
}

// round 5
// speedup vs baseline: 1.4884x; 1.4884x over previous
#include <cuda_runtime.h>
#include <cuda_bf16.h>
#include <cstdint>

#define NN   50000
#define EE   800000
#define RR   8
#define DIN  64
#define DHID 128
#define DOUT 64
#define EPSF 1e-5f
#define NSEG (NN * RR)            // 400000
#define NB   ((NSEG + 255) / 256) // 1563 scan blocks

// ---------------- scratch (device globals; no allocation allowed) ----------------
__device__ float g_S1[NN * RR * DIN];   // [N,8,64] per-(dst,rel) MEANS of x[src]
__device__ int   g_cnt[NSEG];
__device__ int   g_off[NSEG];
__device__ int   g_cursor[NSEG];
__device__ float g_invcnt[NSEG];
__device__ int   g_sorted[EE];
__device__ int   g_bsum[NB];
__device__ int   g_bpre[NB];
__device__ float g_h[NN * DHID];        // layer-1 output [N,128] (post-LN)
__device__ float g_C2[NN * 9 * DOUT];   // [N,9,64]
__device__ int   g_is64;

// bf16 split weights, transposed to [Ncols, K] K-major (16B aligned for uint4 copies)
__device__ __align__(16) __nv_bfloat16 g_B1h[128 * 576];
__device__ __align__(16) __nv_bfloat16 g_B1l[128 * 576];
__device__ __align__(16) __nv_bfloat16 g_B2h[576 * 128];
__device__ __align__(16) __nv_bfloat16 g_B2l[576 * 128];

// ---------------- generic helpers ----------------
__device__ __forceinline__ int ld_idx(const void* p, int i, int is64) {
    if (is64) return (int)(((const long long*)p)[i]);
    return ((const int*)p)[i];
}

__global__ void detect_kernel(const int* __restrict__ ei) {
    int all0 = 1;
    for (int k = 0; k < 32; k++)
        if (ei[2 * k + 1] != 0) all0 = 0;
    g_is64 = all0;
}

__global__ void zero_cnt_kernel() {
    int i = blockIdx.x * 256 + threadIdx.x;
    if (i < NSEG / 4) ((int4*)g_cnt)[i] = make_int4(0, 0, 0, 0);
}

__global__ void count_kernel(const void* __restrict__ ei, const void* __restrict__ et) {
    int e = blockIdx.x * 256 + threadIdx.x;
    if (e >= EE) return;
    int is64 = g_is64;
    int dst = ld_idx(ei, EE + e, is64);
    int r   = ld_idx(et, e, is64);
    atomicAdd(&g_cnt[dst * RR + r], 1);
}

__global__ void scan1_kernel() {
    __shared__ int sm[256];
    int b = blockIdx.x, t = threadIdx.x;
    int i = b * 256 + t;
    int v = (i < NSEG) ? g_cnt[i] : 0;
    sm[t] = v;
    __syncthreads();
    for (int o = 1; o < 256; o <<= 1) {
        int u = (t >= o) ? sm[t - o] : 0;
        __syncthreads();
        sm[t] += u;
        __syncthreads();
    }
    if (i < NSEG) g_off[i] = sm[t] - v;
    if (t == 255) g_bsum[b] = sm[255];
}

__global__ void scan2_kernel() {
    __shared__ int sm[1024];
    int t = threadIdx.x;
    int i0 = 2 * t, i1 = 2 * t + 1;
    int v0 = (i0 < NB) ? g_bsum[i0] : 0;
    int v1 = (i1 < NB) ? g_bsum[i1] : 0;
    int s = v0 + v1;
    sm[t] = s;
    __syncthreads();
    for (int o = 1; o < 1024; o <<= 1) {
        int u = (t >= o) ? sm[t - o] : 0;
        __syncthreads();
        sm[t] += u;
        __syncthreads();
    }
    int e = sm[t] - s;
    if (i0 < NB) g_bpre[i0] = e;
    if (i1 < NB) g_bpre[i1] = e + v0;
}

__global__ void scan3_kernel() {
    int i = blockIdx.x * 256 + threadIdx.x;
    if (i >= NSEG) return;
    int o = g_off[i] + g_bpre[blockIdx.x];
    g_off[i] = o;
    g_cursor[i] = o;
    int c = g_cnt[i];
    g_invcnt[i] = (c > 0) ? (1.0f / (float)c) : 0.0f;
}

__global__ void scatter_pos_kernel(const void* __restrict__ ei, const void* __restrict__ et) {
    int e = blockIdx.x * 256 + threadIdx.x;
    if (e >= EE) return;
    int is64 = g_is64;
    int src = ld_idx(ei, e, is64);
    int dst = ld_idx(ei, EE + e, is64);
    int r   = ld_idx(et, e, is64);
    int pos = atomicAdd(&g_cursor[dst * RR + r], 1);
    g_sorted[pos] = src;
}

// gather1: warp per dst node; S1[dst,r,:] = mean of x[src,:] over segment (dst,r).
__global__ void gather1_kernel(const float* __restrict__ x) {
    int w = blockIdx.x * 8 + (threadIdx.x >> 5);
    if (w >= NN) return;
    int lane = threadIdx.x & 31;
#pragma unroll
    for (int r = 0; r < RR; r++) {
        int seg = w * RR + r;
        int beg = g_off[seg];
        int cnt = g_cnt[seg];
        float inv = g_invcnt[seg];
        float sx = 0.f, sy = 0.f;
        for (int j = 0; j < cnt; j++) {
            int src = __ldg(&g_sorted[beg + j]);
            float2 v = __ldg((const float2*)(x + (size_t)src * DIN + lane * 2));
            sx += v.x; sy += v.y;
        }
        float2 o; o.x = sx * inv; o.y = sy * inv;
        *(float2*)(g_S1 + (size_t)w * 512 + r * 64 + lane * 2) = o;
    }
}

// prep: split + transpose weights to bf16 hi/lo, [Ncols, K]
__global__ void prep_kernel(const float* __restrict__ W1, const float* __restrict__ root1,
                            const float* __restrict__ W2, const float* __restrict__ root2) {
    int idx = blockIdx.x * 256 + threadIdx.x;
    if (idx < 128 * 576) {
        int n = idx / 576, k = idx % 576;
        float v = (k < 512) ? W1[(size_t)k * 128 + n] : root1[(size_t)(k - 512) * 128 + n];
        __nv_bfloat16 h = __float2bfloat16(v);
        g_B1h[idx] = h;
        g_B1l[idx] = __float2bfloat16(v - __bfloat162float(h));
    }
    if (idx < 576 * 128) {
        int j = idx / 128, k = idx % 128;
        int r = j >> 6, col = j & 63;
        float v = (r < 8) ? W2[((size_t)r * 128 + k) * 64 + col] : root2[(size_t)k * 64 + col];
        __nv_bfloat16 h = __float2bfloat16(v);
        g_B2h[idx] = h;
        g_B2l[idx] = __float2bfloat16(v - __bfloat162float(h));
    }
}

// ---------------- mma.sync helpers ----------------
__device__ __forceinline__ uint32_t pack2(float a, float b) {
    __nv_bfloat162 h = __floats2bfloat162_rn(a, b);
    return *reinterpret_cast<uint32_t*>(&h);
}

__device__ __forceinline__ void mma_bf16(float* c, uint32_t a0, uint32_t a1, uint32_t a2,
                                         uint32_t a3, uint32_t b0, uint32_t b1) {
    asm volatile(
        "mma.sync.aligned.m16n8k16.row.col.f32.bf16.bf16.f32 "
        "{%0,%1,%2,%3}, {%4,%5,%6,%7}, {%8,%9}, {%0,%1,%2,%3};"
        : "+f"(c[0]), "+f"(c[1]), "+f"(c[2]), "+f"(c[3])
        : "r"(a0), "r"(a1), "r"(a2), "r"(a3), "r"(b0), "r"(b1));
}

// SMEM tile: [128 rows][72 bf16] per plane (pad 8 -> conflict-free fragment LDS)
#define LDT 72
#define PLANE (128 * LDT)                       // bf16 elements per plane
#define GEMM_SMEM (4 * PLANE * 2 + 2 * 128 * 4) // 4 planes + red[2][128]

// Split 8 float4 (32 floats) into hi/lo bf16 and store to SMEM row segment.
__device__ __forceinline__ void split_store32(const float* src, bool valid,
                                              __nv_bfloat16* dh, __nv_bfloat16* dl) {
#pragma unroll
    for (int i = 0; i < 8; i++) {
        float4 v = valid ? *(const float4*)(src + i * 4) : make_float4(0.f, 0.f, 0.f, 0.f);
        uint2 hi, lo;
        hi.x = pack2(v.x, v.y);
        hi.y = pack2(v.z, v.w);
        __nv_bfloat162 t0 = *(__nv_bfloat162*)&hi.x;
        __nv_bfloat162 t1 = *(__nv_bfloat162*)&hi.y;
        lo.x = pack2(v.x - __bfloat162float(t0.x), v.y - __bfloat162float(t0.y));
        lo.y = pack2(v.z - __bfloat162float(t1.x), v.w - __bfloat162float(t1.y));
        *(uint2*)(dh + i * 4) = hi;
        *(uint2*)(dl + i * 4) = lo;
    }
}

// ================= GEMM1 (mma.sync): h = LN(leaky([S1|x] @ B1 + bias1)) =================
// grid 391, block 256. BM=128, BN=128, K=576 in 9 chunks of BK=64.
__global__ __launch_bounds__(256, 2) void gemm1_mma(
    const float* __restrict__ x, const float* __restrict__ bias1,
    const float* __restrict__ gamma1, const float* __restrict__ beta1) {
    extern __shared__ char smraw[];
    __nv_bfloat16* Ah = (__nv_bfloat16*)smraw;
    __nv_bfloat16* Al = Ah + PLANE;
    __nv_bfloat16* Bh = Al + PLANE;
    __nv_bfloat16* Bl = Bh + PLANE;
    float* red = (float*)(Bl + PLANE);  // [2][128]

    int tid = threadIdx.x, lane = tid & 31, wid = tid >> 5;
    int n0 = blockIdx.x * 128;
    int ldrow = tid >> 1, half = tid & 1;
    int nrow = n0 + ldrow;
    bool avalid = nrow < NN;
    int wm = (wid >> 1) * 32, wn = (wid & 1) * 64;
    int gid = lane >> 2, t4 = lane & 3;

    float acc[2][8][4];
#pragma unroll
    for (int mt = 0; mt < 2; mt++)
#pragma unroll
        for (int nt = 0; nt < 8; nt++)
#pragma unroll
            for (int q = 0; q < 4; q++) acc[mt][nt][q] = 0.f;

    for (int c = 0; c < 9; c++) {
        if (c) __syncthreads();
        // A: fp32 -> hi/lo split
        const float* asrc = (c < 8) ? (g_S1 + (size_t)nrow * 512 + c * 64 + half * 32)
                                    : (x + (size_t)nrow * 64 + half * 32);
        split_store32(asrc, avalid, Ah + ldrow * LDT + half * 32, Al + ldrow * LDT + half * 32);
        // B: copy pre-split bf16 (ldrow = output-col index 0..127)
        {
            const uint4* sh = (const uint4*)(g_B1h + (size_t)ldrow * 576 + c * 64 + half * 32);
            const uint4* sl = (const uint4*)(g_B1l + (size_t)ldrow * 576 + c * 64 + half * 32);
            uint4* dh = (uint4*)(Bh + ldrow * LDT + half * 32);
            uint4* dl = (uint4*)(Bl + ldrow * LDT + half * 32);
#pragma unroll
            for (int i = 0; i < 4; i++) { dh[i] = sh[i]; dl[i] = sl[i]; }
        }
        __syncthreads();
#pragma unroll
        for (int ks = 0; ks < 4; ks++) {
            int kb = ks * 16 + t4 * 2;
            uint32_t Afh[2][4], Afl[2][4];
#pragma unroll
            for (int mt = 0; mt < 2; mt++) {
                const __nv_bfloat16* pa = Ah + (wm + mt * 16 + gid) * LDT;
                const __nv_bfloat16* pl = Al + (wm + mt * 16 + gid) * LDT;
                Afh[mt][0] = *(const uint32_t*)(pa + kb);
                Afh[mt][1] = *(const uint32_t*)(pa + 8 * LDT + kb);
                Afh[mt][2] = *(const uint32_t*)(pa + kb + 8);
                Afh[mt][3] = *(const uint32_t*)(pa + 8 * LDT + kb + 8);
                Afl[mt][0] = *(const uint32_t*)(pl + kb);
                Afl[mt][1] = *(const uint32_t*)(pl + 8 * LDT + kb);
                Afl[mt][2] = *(const uint32_t*)(pl + kb + 8);
                Afl[mt][3] = *(const uint32_t*)(pl + 8 * LDT + kb + 8);
            }
#pragma unroll
            for (int nt = 0; nt < 8; nt++) {
                const __nv_bfloat16* pb = Bh + (wn + nt * 8 + gid) * LDT + kb;
                const __nv_bfloat16* pbl = Bl + (wn + nt * 8 + gid) * LDT + kb;
                uint32_t bh0 = *(const uint32_t*)pb, bh1 = *(const uint32_t*)(pb + 8);
                uint32_t bl0 = *(const uint32_t*)pbl, bl1 = *(const uint32_t*)(pbl + 8);
#pragma unroll
                for (int mt = 0; mt < 2; mt++) {
                    mma_bf16(acc[mt][nt], Afh[mt][0], Afh[mt][1], Afh[mt][2], Afh[mt][3], bh0, bh1);
                    mma_bf16(acc[mt][nt], Afh[mt][0], Afh[mt][1], Afh[mt][2], Afh[mt][3], bl0, bl1);
                    mma_bf16(acc[mt][nt], Afl[mt][0], Afl[mt][1], Afl[mt][2], Afl[mt][3], bh0, bh1);
                }
            }
        }
    }

    // ---- epilogue: bias + leaky + LN (rows split across warpN pairs) ----
#pragma unroll
    for (int nt = 0; nt < 8; nt++) {
        int col = wn + nt * 8 + t4 * 2;
        float b0 = __ldg(&bias1[col]), b1 = __ldg(&bias1[col + 1]);
#pragma unroll
        for (int mt = 0; mt < 2; mt++) {
            float* cc = acc[mt][nt];
            cc[0] += b0; cc[1] += b1; cc[2] += b0; cc[3] += b1;
#pragma unroll
            for (int q = 0; q < 4; q++) cc[q] = (cc[q] >= 0.f) ? cc[q] : 0.2f * cc[q];
        }
    }
    int wnid = wid & 1;
    // row sums
#pragma unroll
    for (int mt = 0; mt < 2; mt++) {
        float sA = 0.f, sB = 0.f;
#pragma unroll
        for (int nt = 0; nt < 8; nt++) {
            sA += acc[mt][nt][0] + acc[mt][nt][1];
            sB += acc[mt][nt][2] + acc[mt][nt][3];
        }
        sA += __shfl_xor_sync(0xFFFFFFFFu, sA, 1);
        sA += __shfl_xor_sync(0xFFFFFFFFu, sA, 2);
        sB += __shfl_xor_sync(0xFFFFFFFFu, sB, 1);
        sB += __shfl_xor_sync(0xFFFFFFFFu, sB, 2);
        if (t4 == 0) {
            red[wnid * 128 + wm + mt * 16 + gid] = sA;
            red[wnid * 128 + wm + mt * 16 + gid + 8] = sB;
        }
    }
    __syncthreads();
    float muA[2], muB[2];
#pragma unroll
    for (int mt = 0; mt < 2; mt++) {
        int rA = wm + mt * 16 + gid;
        muA[mt] = (red[rA] + red[128 + rA]) * (1.f / 128.f);
        muB[mt] = (red[rA + 8] + red[128 + rA + 8]) * (1.f / 128.f);
    }
    __syncthreads();
    // row sum of squares
#pragma unroll
    for (int mt = 0; mt < 2; mt++) {
        float sA = 0.f, sB = 0.f;
#pragma unroll
        for (int nt = 0; nt < 8; nt++) {
            float d0 = acc[mt][nt][0] - muA[mt], d1 = acc[mt][nt][1] - muA[mt];
            float d2 = acc[mt][nt][2] - muB[mt], d3 = acc[mt][nt][3] - muB[mt];
            sA += d0 * d0 + d1 * d1;
            sB += d2 * d2 + d3 * d3;
        }
        sA += __shfl_xor_sync(0xFFFFFFFFu, sA, 1);
        sA += __shfl_xor_sync(0xFFFFFFFFu, sA, 2);
        sB += __shfl_xor_sync(0xFFFFFFFFu, sB, 1);
        sB += __shfl_xor_sync(0xFFFFFFFFu, sB, 2);
        if (t4 == 0) {
            red[wnid * 128 + wm + mt * 16 + gid] = sA;
            red[wnid * 128 + wm + mt * 16 + gid + 8] = sB;
        }
    }
    __syncthreads();
#pragma unroll
    for (int mt = 0; mt < 2; mt++) {
        int rA = wm + mt * 16 + gid;
        float rsA = rsqrtf((red[rA] + red[128 + rA]) * (1.f / 128.f) + EPSF);
        float rsB = rsqrtf((red[rA + 8] + red[128 + rA + 8]) * (1.f / 128.f) + EPSF);
        int nA = n0 + rA, nB = nA + 8;
#pragma unroll
        for (int nt = 0; nt < 8; nt++) {
            int col = wn + nt * 8 + t4 * 2;
            float g0 = __ldg(&gamma1[col]), g1 = __ldg(&gamma1[col + 1]);
            float be0 = __ldg(&beta1[col]), be1 = __ldg(&beta1[col + 1]);
            if (nA < NN) {
                float2 o;
                o.x = (acc[mt][nt][0] - muA[mt]) * rsA * g0 + be0;
                o.y = (acc[mt][nt][1] - muA[mt]) * rsA * g1 + be1;
                *(float2*)(g_h + (size_t)nA * 128 + col) = o;
            }
            if (nB < NN) {
                float2 o;
                o.x = (acc[mt][nt][2] - muB[mt]) * rsB * g0 + be0;
                o.y = (acc[mt][nt][3] - muB[mt]) * rsB * g1 + be1;
                *(float2*)(g_h + (size_t)nB * 128 + col) = o;
            }
        }
    }
}

// ================= GEMM2 (mma.sync): C2[:, j] = h @ B2, j tiled by 128 =================
// grid (391, 5). K=128 in 2 chunks of 64. bias2 on cols >= 512.
__global__ __launch_bounds__(256, 2) void gemm2_mma(const float* __restrict__ bias2) {
    extern __shared__ char smraw[];
    __nv_bfloat16* Ah = (__nv_bfloat16*)smraw;
    __nv_bfloat16* Al = Ah + PLANE;
    __nv_bfloat16* Bh = Al + PLANE;
    __nv_bfloat16* Bl = Bh + PLANE;

    int tid = threadIdx.x, lane = tid & 31, wid = tid >> 5;
    int n0 = blockIdx.x * 128;
    int j0 = blockIdx.y * 128;
    int ldrow = tid >> 1, half = tid & 1;
    int nrow = n0 + ldrow;
    bool avalid = nrow < NN;
    bool bvalid = (j0 + ldrow) < 576;
    int wm = (wid >> 1) * 32, wn = (wid & 1) * 64;
    int gid = lane >> 2, t4 = lane & 3;

    float acc[2][8][4];
#pragma unroll
    for (int mt = 0; mt < 2; mt++)
#pragma unroll
        for (int nt = 0; nt < 8; nt++)
#pragma unroll
            for (int q = 0; q < 4; q++) acc[mt][nt][q] = 0.f;

#pragma unroll
    for (int c = 0; c < 2; c++) {
        if (c) __syncthreads();
        split_store32(g_h + (size_t)nrow * 128 + c * 64 + half * 32, avalid,
                      Ah + ldrow * LDT + half * 32, Al + ldrow * LDT + half * 32);
        {
            uint4* dh = (uint4*)(Bh + ldrow * LDT + half * 32);
            uint4* dl = (uint4*)(Bl + ldrow * LDT + half * 32);
            if (bvalid) {
                const uint4* sh = (const uint4*)(g_B2h + (size_t)(j0 + ldrow) * 128 + c * 64 + half * 32);
                const uint4* sl = (const uint4*)(g_B2l + (size_t)(j0 + ldrow) * 128 + c * 64 + half * 32);
#pragma unroll
                for (int i = 0; i < 4; i++) { dh[i] = sh[i]; dl[i] = sl[i]; }
            } else {
                uint4 z = make_uint4(0, 0, 0, 0);
#pragma unroll
                for (int i = 0; i < 4; i++) { dh[i] = z; dl[i] = z; }
            }
        }
        __syncthreads();
#pragma unroll
        for (int ks = 0; ks < 4; ks++) {
            int kb = ks * 16 + t4 * 2;
            uint32_t Afh[2][4], Afl[2][4];
#pragma unroll
            for (int mt = 0; mt < 2; mt++) {
                const __nv_bfloat16* pa = Ah + (wm + mt * 16 + gid) * LDT;
                const __nv_bfloat16* pl = Al + (wm + mt * 16 + gid) * LDT;
                Afh[mt][0] = *(const uint32_t*)(pa + kb);
                Afh[mt][1] = *(const uint32_t*)(pa + 8 * LDT + kb);
                Afh[mt][2] = *(const uint32_t*)(pa + kb + 8);
                Afh[mt][3] = *(const uint32_t*)(pa + 8 * LDT + kb + 8);
                Afl[mt][0] = *(const uint32_t*)(pl + kb);
                Afl[mt][1] = *(const uint32_t*)(pl + 8 * LDT + kb);
                Afl[mt][2] = *(const uint32_t*)(pl + kb + 8);
                Afl[mt][3] = *(const uint32_t*)(pl + 8 * LDT + kb + 8);
            }
#pragma unroll
            for (int nt = 0; nt < 8; nt++) {
                const __nv_bfloat16* pb = Bh + (wn + nt * 8 + gid) * LDT + kb;
                const __nv_bfloat16* pbl = Bl + (wn + nt * 8 + gid) * LDT + kb;
                uint32_t bh0 = *(const uint32_t*)pb, bh1 = *(const uint32_t*)(pb + 8);
                uint32_t bl0 = *(const uint32_t*)pbl, bl1 = *(const uint32_t*)(pbl + 8);
#pragma unroll
                for (int mt = 0; mt < 2; mt++) {
                    mma_bf16(acc[mt][nt], Afh[mt][0], Afh[mt][1], Afh[mt][2], Afh[mt][3], bh0, bh1);
                    mma_bf16(acc[mt][nt], Afh[mt][0], Afh[mt][1], Afh[mt][2], Afh[mt][3], bl0, bl1);
                    mma_bf16(acc[mt][nt], Afl[mt][0], Afl[mt][1], Afl[mt][2], Afl[mt][3], bh0, bh1);
                }
            }
        }
    }

    // epilogue: store C2, bias2 on cols >= 512
#pragma unroll
    for (int mt = 0; mt < 2; mt++) {
        int nA = n0 + wm + mt * 16 + gid;
        int nB = nA + 8;
#pragma unroll
        for (int nt = 0; nt < 8; nt++) {
            int j = j0 + wn + nt * 8 + t4 * 2;
            if (j >= 576) continue;
            float b0 = 0.f, b1 = 0.f;
            if (j >= 512) { b0 = __ldg(&bias2[j - 512]); b1 = __ldg(&bias2[j - 511]); }
            if (nA < NN) {
                float2 o; o.x = acc[mt][nt][0] + b0; o.y = acc[mt][nt][1] + b1;
                *(float2*)(g_C2 + (size_t)nA * 576 + j) = o;
            }
            if (nB < NN) {
                float2 o; o.x = acc[mt][nt][2] + b0; o.y = acc[mt][nt][3] + b1;
                *(float2*)(g_C2 + (size_t)nB * 576 + j) = o;
            }
        }
    }
}

// gather2 + final LayerNorm fused: warp per dst.
__global__ void gather2_kernel(const float* __restrict__ gamma, const float* __restrict__ beta,
                               float* __restrict__ out) {
    int w = blockIdx.x * 8 + (threadIdx.x >> 5);
    if (w >= NN) return;
    int lane = threadIdx.x & 31;
    float2 acc = *(const float2*)(g_C2 + (size_t)w * 576 + 512 + lane * 2);
#pragma unroll
    for (int r = 0; r < RR; r++) {
        int seg = w * RR + r;
        int cnt = g_cnt[seg];
        if (cnt == 0) continue;
        int beg = g_off[seg];
        float inv = g_invcnt[seg];
        float sx = 0.f, sy = 0.f;
        for (int j = 0; j < cnt; j++) {
            int src = __ldg(&g_sorted[beg + j]);
            float2 v = __ldg((const float2*)(g_C2 + (size_t)src * 576 + r * 64 + lane * 2));
            sx += v.x; sy += v.y;
        }
        acc.x += sx * inv;
        acc.y += sy * inv;
    }
    float s = acc.x + acc.y;
#pragma unroll
    for (int o = 16; o; o >>= 1) s += __shfl_xor_sync(0xFFFFFFFFu, s, o);
    float mu = s * (1.f / 64.f);
    float dx = acc.x - mu, dy = acc.y - mu;
    float sq = dx * dx + dy * dy;
#pragma unroll
    for (int o = 16; o; o >>= 1) sq += __shfl_xor_sync(0xFFFFFFFFu, sq, o);
    float rstd = rsqrtf(sq * (1.f / 64.f) + EPSF);
    float2 g = ((const float2*)gamma)[lane];
    float2 b = ((const float2*)beta)[lane];
    float2 o2;
    o2.x = dx * rstd * g.x + b.x;
    o2.y = dy * rstd * g.y + b.y;
    ((float2*)out)[(size_t)w * 32 + lane] = o2;
}

// ---------------- launch ----------------
extern "C" void kernel_launch(void* const* d_in, const int* in_sizes, int n_in,
                              void* d_out, int out_size) {
    const float* x      = (const float*)d_in[0];
    const void*  ei     = d_in[1];
    const void*  et     = d_in[2];
    const float* W1     = (const float*)d_in[3];
    const float* root1  = (const float*)d_in[4];
    const float* bias1  = (const float*)d_in[5];
    const float* gamma1 = (const float*)d_in[6];
    const float* beta1  = (const float*)d_in[7];
    const float* W2     = (const float*)d_in[8];
    const float* root2  = (const float*)d_in[9];
    const float* bias2  = (const float*)d_in[10];
    const float* gamma2 = (const float*)d_in[11];
    const float* beta2  = (const float*)d_in[12];
    float* out = (float*)d_out;

    cudaFuncSetAttribute(gemm1_mma, cudaFuncAttributeMaxDynamicSharedMemorySize, GEMM_SMEM);
    cudaFuncSetAttribute(gemm2_mma, cudaFuncAttributeMaxDynamicSharedMemorySize, GEMM_SMEM);

    detect_kernel<<<1, 1>>>((const int*)ei);
    zero_cnt_kernel<<<(NSEG / 4 + 255) / 256, 256>>>();
    count_kernel<<<(EE + 255) / 256, 256>>>(ei, et);
    scan1_kernel<<<NB, 256>>>();
    scan2_kernel<<<1, 1024>>>();
    scan3_kernel<<<NB, 256>>>();
    scatter_pos_kernel<<<(EE + 255) / 256, 256>>>(ei, et);
    prep_kernel<<<(128 * 576 + 255) / 256, 256>>>(W1, root1, W2, root2);
    gather1_kernel<<<(NN + 7) / 8, 256>>>(x);
    gemm1_mma<<<(NN + 127) / 128, 256, GEMM_SMEM>>>(x, bias1, gamma1, beta1);
    gemm2_mma<<<dim3((NN + 127) / 128, 5), 256, GEMM_SMEM>>>(bias2);
    gather2_kernel<<<(NN + 7) / 8, 256>>>(gamma2, beta2, out);
}

// round 6
// speedup vs baseline: 1.8125x; 1.2177x over previous
#include <cuda_runtime.h>
#include <cuda_bf16.h>
#include <cstdint>

#define NN   50000
#define EE   800000
#define RR   8
#define DIN  64
#define DHID 128
#define DOUT 64
#define EPSF 1e-5f
#define NSEG (NN * RR)            // 400000
#define NB   ((NSEG + 255) / 256) // 1563 scan blocks

// ---------------- scratch (device globals; no allocation allowed) ----------------
__device__ int   g_cnt[NSEG];
__device__ int   g_off[NSEG];
__device__ int   g_cursor[NSEG];
__device__ float g_invcnt[NSEG];
__device__ int   g_sorted[EE];
__device__ int   g_bsum[NB];
__device__ int   g_bpre[NB];
__device__ float g_C2[NN * 9 * DOUT];   // [N,9,64]
__device__ int   g_is64;

// split bf16 activations / weights (16B aligned for cp.async)
__device__ __align__(16) __nv_bfloat16 g_A1h[NN * 576];  // [N,576]: 8x64 rel means | x
__device__ __align__(16) __nv_bfloat16 g_A1l[NN * 576];
__device__ __align__(16) __nv_bfloat16 g_Hh[NN * 128];   // layer-1 output (post-LN)
__device__ __align__(16) __nv_bfloat16 g_Hl[NN * 128];
__device__ __align__(16) __nv_bfloat16 g_B1h[128 * 576]; // [Ncols,K]
__device__ __align__(16) __nv_bfloat16 g_B1l[128 * 576];
__device__ __align__(16) __nv_bfloat16 g_B2h[576 * 128];
__device__ __align__(16) __nv_bfloat16 g_B2l[576 * 128];

// ---------------- generic helpers ----------------
__device__ __forceinline__ int ld_idx(const void* p, int i, int is64) {
    if (is64) return (int)(((const long long*)p)[i]);
    return ((const int*)p)[i];
}

__global__ void detect_kernel(const int* __restrict__ ei) {
    int all0 = 1;
    for (int k = 0; k < 32; k++)
        if (ei[2 * k + 1] != 0) all0 = 0;
    g_is64 = all0;
}

__global__ void zero_cnt_kernel() {
    int i = blockIdx.x * 256 + threadIdx.x;
    if (i < NSEG / 4) ((int4*)g_cnt)[i] = make_int4(0, 0, 0, 0);
}

__global__ void count_kernel(const void* __restrict__ ei, const void* __restrict__ et) {
    int e = blockIdx.x * 256 + threadIdx.x;
    if (e >= EE) return;
    int is64 = g_is64;
    int dst = ld_idx(ei, EE + e, is64);
    int r   = ld_idx(et, e, is64);
    atomicAdd(&g_cnt[dst * RR + r], 1);
}

__global__ void scan1_kernel() {
    __shared__ int sm[256];
    int b = blockIdx.x, t = threadIdx.x;
    int i = b * 256 + t;
    int v = (i < NSEG) ? g_cnt[i] : 0;
    sm[t] = v;
    __syncthreads();
    for (int o = 1; o < 256; o <<= 1) {
        int u = (t >= o) ? sm[t - o] : 0;
        __syncthreads();
        sm[t] += u;
        __syncthreads();
    }
    if (i < NSEG) g_off[i] = sm[t] - v;
    if (t == 255) g_bsum[b] = sm[255];
}

__global__ void scan2_kernel() {
    __shared__ int sm[1024];
    int t = threadIdx.x;
    int i0 = 2 * t, i1 = 2 * t + 1;
    int v0 = (i0 < NB) ? g_bsum[i0] : 0;
    int v1 = (i1 < NB) ? g_bsum[i1] : 0;
    int s = v0 + v1;
    sm[t] = s;
    __syncthreads();
    for (int o = 1; o < 1024; o <<= 1) {
        int u = (t >= o) ? sm[t - o] : 0;
        __syncthreads();
        sm[t] += u;
        __syncthreads();
    }
    int e = sm[t] - s;
    if (i0 < NB) g_bpre[i0] = e;
    if (i1 < NB) g_bpre[i1] = e + v0;
}

__global__ void scan3_kernel() {
    int i = blockIdx.x * 256 + threadIdx.x;
    if (i >= NSEG) return;
    int o = g_off[i] + g_bpre[blockIdx.x];
    g_off[i] = o;
    g_cursor[i] = o;
    int c = g_cnt[i];
    g_invcnt[i] = (c > 0) ? (1.0f / (float)c) : 0.0f;
}

__global__ void scatter_pos_kernel(const void* __restrict__ ei, const void* __restrict__ et) {
    int e = blockIdx.x * 256 + threadIdx.x;
    if (e >= EE) return;
    int is64 = g_is64;
    int src = ld_idx(ei, e, is64);
    int dst = ld_idx(ei, EE + e, is64);
    int r   = ld_idx(et, e, is64);
    int pos = atomicAdd(&g_cursor[dst * RR + r], 1);
    g_sorted[pos] = src;
}

__device__ __forceinline__ void split_write2(float a, float b,
                                             __nv_bfloat16* ph, __nv_bfloat16* pl) {
    __nv_bfloat162 h = __floats2bfloat162_rn(a, b);
    *(__nv_bfloat162*)ph = h;
    __nv_bfloat162 l = __floats2bfloat162_rn(a - __bfloat162float(h.x),
                                             b - __bfloat162float(h.y));
    *(__nv_bfloat162*)pl = l;
}

// gather1: warp per dst; A1[dst, r*64:...] = split(mean x[src]); cols 512.. = split(x[dst]).
__global__ void gather1_kernel(const float* __restrict__ x) {
    int w = blockIdx.x * 8 + (threadIdx.x >> 5);
    if (w >= NN) return;
    int lane = threadIdx.x & 31;
#pragma unroll
    for (int r = 0; r < RR; r++) {
        int seg = w * RR + r;
        int beg = g_off[seg];
        int cnt = g_cnt[seg];
        float inv = g_invcnt[seg];
        float sx = 0.f, sy = 0.f;
        for (int j = 0; j < cnt; j++) {
            int src = __ldg(&g_sorted[beg + j]);
            float2 v = __ldg((const float2*)(x + (size_t)src * DIN + lane * 2));
            sx += v.x; sy += v.y;
        }
        size_t o = (size_t)w * 576 + r * 64 + lane * 2;
        split_write2(sx * inv, sy * inv, g_A1h + o, g_A1l + o);
    }
    float2 xv = *(const float2*)(x + (size_t)w * 64 + lane * 2);
    size_t o = (size_t)w * 576 + 512 + lane * 2;
    split_write2(xv.x, xv.y, g_A1h + o, g_A1l + o);
}

// prep: split + transpose weights to bf16 hi/lo, [Ncols, K]
__global__ void prep_kernel(const float* __restrict__ W1, const float* __restrict__ root1,
                            const float* __restrict__ W2, const float* __restrict__ root2) {
    int idx = blockIdx.x * 256 + threadIdx.x;
    if (idx < 128 * 576) {
        int n = idx / 576, k = idx % 576;
        float v = (k < 512) ? W1[(size_t)k * 128 + n] : root1[(size_t)(k - 512) * 128 + n];
        __nv_bfloat16 h = __float2bfloat16(v);
        g_B1h[idx] = h;
        g_B1l[idx] = __float2bfloat16(v - __bfloat162float(h));
    }
    if (idx < 576 * 128) {
        int j = idx / 128, k = idx % 128;
        int r = j >> 6, col = j & 63;
        float v = (r < 8) ? W2[((size_t)r * 128 + k) * 64 + col] : root2[(size_t)k * 64 + col];
        __nv_bfloat16 h = __float2bfloat16(v);
        g_B2h[idx] = h;
        g_B2l[idx] = __float2bfloat16(v - __bfloat162float(h));
    }
}

// ---------------- mma.sync / cp.async helpers ----------------
__device__ __forceinline__ void mma_bf16(float* c, uint32_t a0, uint32_t a1, uint32_t a2,
                                         uint32_t a3, uint32_t b0, uint32_t b1) {
    asm volatile(
        "mma.sync.aligned.m16n8k16.row.col.f32.bf16.bf16.f32 "
        "{%0,%1,%2,%3}, {%4,%5,%6,%7}, {%8,%9}, {%0,%1,%2,%3};"
        : "+f"(c[0]), "+f"(c[1]), "+f"(c[2]), "+f"(c[3])
        : "r"(a0), "r"(a1), "r"(a2), "r"(a3), "r"(b0), "r"(b1));
}

__device__ __forceinline__ uint32_t smem_u32(const void* p) {
    uint32_t a;
    asm("{ .reg .u64 t; cvta.to.shared.u64 t, %1; cvt.u32.u64 %0, t; }" : "=r"(a) : "l"(p));
    return a;
}

__device__ __forceinline__ void cp16z(uint32_t dst, const void* src, bool pred) {
    int sz = pred ? 16 : 0;
    asm volatile("cp.async.ca.shared.global [%0], [%1], 16, %2;"
                 :: "r"(dst), "l"(__cvta_generic_to_global(src)), "r"(sz) : "memory");
}
#define CP_COMMIT() asm volatile("cp.async.commit_group;" ::: "memory")
#define CP_WAIT(N)  asm volatile("cp.async.wait_group %0;" :: "n"(N) : "memory")

// SMEM tile: 4 planes (Ah, Al, Bh, Bl), each [128 rows][72 bf16] (144B stride)
#define LDT 72
#define PLANE_B (128 * LDT * 2)              // bytes per plane
#define STAGE_B (4 * PLANE_B)                // 73728 bytes
#define GEMM_SMEM (2 * STAGE_B + 2 * 128 * 4)

// Load one K=64 chunk (4 planes) via cp.async. KA = A row stride, KB = B row stride.
template <int KA, int KB>
__device__ __forceinline__ void load_chunk(char* stage, int n0, int c,
                                           const __nv_bfloat16* A1h, const __nv_bfloat16* A1l,
                                           const __nv_bfloat16* B1h, const __nv_bfloat16* B1l,
                                           int brow0, int bmax) {
#pragma unroll
    for (int i = 0; i < 16; i++) {
        int l = threadIdx.x + i * 256;       // 0..4095
        int plane = l >> 10, rem = l & 1023;
        int row = rem >> 3, seg = rem & 7;
        uint32_t dst = smem_u32(stage + plane * PLANE_B + row * (LDT * 2) + seg * 16);
        if (plane < 2) {
            int n = n0 + row;
            bool v = n < NN;
            const __nv_bfloat16* s = (plane == 0 ? A1h : A1l) +
                                     (size_t)(v ? n : 0) * KA + c * 64 + seg * 8;
            cp16z(dst, s, v);
        } else {
            int j = brow0 + row;
            bool v = j < bmax;
            const __nv_bfloat16* s = (plane == 2 ? B1h : B1l) +
                                     (size_t)(v ? j : 0) * KB + c * 64 + seg * 8;
            cp16z(dst, s, v);
        }
    }
}

// Compute one K=64 chunk from a stage (3-term split MMA into acc[2][8][4]).
__device__ __forceinline__ void compute_chunk(const char* stage, int wm, int wn,
                                              int gid, int t4, float acc[2][8][4]) {
    const __nv_bfloat16* Ah = (const __nv_bfloat16*)stage;
    const __nv_bfloat16* Al = (const __nv_bfloat16*)(stage + PLANE_B);
    const __nv_bfloat16* Bh = (const __nv_bfloat16*)(stage + 2 * PLANE_B);
    const __nv_bfloat16* Bl = (const __nv_bfloat16*)(stage + 3 * PLANE_B);
#pragma unroll
    for (int ks = 0; ks < 4; ks++) {
        int kb = ks * 16 + t4 * 2;
        uint32_t Afh[2][4], Afl[2][4];
#pragma unroll
        for (int mt = 0; mt < 2; mt++) {
            const __nv_bfloat16* pa = Ah + (wm + mt * 16 + gid) * LDT;
            const __nv_bfloat16* pl = Al + (wm + mt * 16 + gid) * LDT;
            Afh[mt][0] = *(const uint32_t*)(pa + kb);
            Afh[mt][1] = *(const uint32_t*)(pa + 8 * LDT + kb);
            Afh[mt][2] = *(const uint32_t*)(pa + kb + 8);
            Afh[mt][3] = *(const uint32_t*)(pa + 8 * LDT + kb + 8);
            Afl[mt][0] = *(const uint32_t*)(pl + kb);
            Afl[mt][1] = *(const uint32_t*)(pl + 8 * LDT + kb);
            Afl[mt][2] = *(const uint32_t*)(pl + kb + 8);
            Afl[mt][3] = *(const uint32_t*)(pl + 8 * LDT + kb + 8);
        }
#pragma unroll
        for (int nt = 0; nt < 8; nt++) {
            const __nv_bfloat16* pb = Bh + (wn + nt * 8 + gid) * LDT + kb;
            const __nv_bfloat16* pbl = Bl + (wn + nt * 8 + gid) * LDT + kb;
            uint32_t bh0 = *(const uint32_t*)pb, bh1 = *(const uint32_t*)(pb + 8);
            uint32_t bl0 = *(const uint32_t*)pbl, bl1 = *(const uint32_t*)(pbl + 8);
#pragma unroll
            for (int mt = 0; mt < 2; mt++) {
                mma_bf16(acc[mt][nt], Afh[mt][0], Afh[mt][1], Afh[mt][2], Afh[mt][3], bh0, bh1);
                mma_bf16(acc[mt][nt], Afh[mt][0], Afh[mt][1], Afh[mt][2], Afh[mt][3], bl0, bl1);
                mma_bf16(acc[mt][nt], Afl[mt][0], Afl[mt][1], Afl[mt][2], Afl[mt][3], bh0, bh1);
            }
        }
    }
}

// ================= GEMM1: h = LN(leaky(A1 @ B1 + bias1)), split-bf16 output =================
__global__ __launch_bounds__(256) void gemm1_mma(
    const float* __restrict__ bias1,
    const float* __restrict__ gamma1, const float* __restrict__ beta1) {
    extern __shared__ char smraw[];
    char* stg[2] = { smraw, smraw + STAGE_B };
    float* red = (float*)(smraw + 2 * STAGE_B);  // [2][128]

    int tid = threadIdx.x, lane = tid & 31, wid = tid >> 5;
    int n0 = blockIdx.x * 128;
    int wm = (wid >> 1) * 32, wn = (wid & 1) * 64;
    int gid = lane >> 2, t4 = lane & 3;

    float acc[2][8][4];
#pragma unroll
    for (int mt = 0; mt < 2; mt++)
#pragma unroll
        for (int nt = 0; nt < 8; nt++)
#pragma unroll
            for (int q = 0; q < 4; q++) acc[mt][nt][q] = 0.f;

    load_chunk<576, 576>(stg[0], n0, 0, g_A1h, g_A1l, g_B1h, g_B1l, 0, 128);
    CP_COMMIT();
    for (int c = 0; c < 9; c++) {
        if (c + 1 < 9) {
            load_chunk<576, 576>(stg[(c + 1) & 1], n0, c + 1, g_A1h, g_A1l, g_B1h, g_B1l, 0, 128);
            CP_COMMIT();
            CP_WAIT(1);
        } else {
            CP_WAIT(0);
        }
        __syncthreads();
        compute_chunk(stg[c & 1], wm, wn, gid, t4, acc);
        __syncthreads();
    }

    // ---- epilogue: bias + leaky + LN ----
#pragma unroll
    for (int nt = 0; nt < 8; nt++) {
        int col = wn + nt * 8 + t4 * 2;
        float b0 = __ldg(&bias1[col]), b1 = __ldg(&bias1[col + 1]);
#pragma unroll
        for (int mt = 0; mt < 2; mt++) {
            float* cc = acc[mt][nt];
            cc[0] += b0; cc[1] += b1; cc[2] += b0; cc[3] += b1;
#pragma unroll
            for (int q = 0; q < 4; q++) cc[q] = (cc[q] >= 0.f) ? cc[q] : 0.2f * cc[q];
        }
    }
    int wnid = wid & 1;
#pragma unroll
    for (int mt = 0; mt < 2; mt++) {
        float sA = 0.f, sB = 0.f;
#pragma unroll
        for (int nt = 0; nt < 8; nt++) {
            sA += acc[mt][nt][0] + acc[mt][nt][1];
            sB += acc[mt][nt][2] + acc[mt][nt][3];
        }
        sA += __shfl_xor_sync(0xFFFFFFFFu, sA, 1);
        sA += __shfl_xor_sync(0xFFFFFFFFu, sA, 2);
        sB += __shfl_xor_sync(0xFFFFFFFFu, sB, 1);
        sB += __shfl_xor_sync(0xFFFFFFFFu, sB, 2);
        if (t4 == 0) {
            red[wnid * 128 + wm + mt * 16 + gid] = sA;
            red[wnid * 128 + wm + mt * 16 + gid + 8] = sB;
        }
    }
    __syncthreads();
    float muA[2], muB[2];
#pragma unroll
    for (int mt = 0; mt < 2; mt++) {
        int rA = wm + mt * 16 + gid;
        muA[mt] = (red[rA] + red[128 + rA]) * (1.f / 128.f);
        muB[mt] = (red[rA + 8] + red[128 + rA + 8]) * (1.f / 128.f);
    }
    __syncthreads();
#pragma unroll
    for (int mt = 0; mt < 2; mt++) {
        float sA = 0.f, sB = 0.f;
#pragma unroll
        for (int nt = 0; nt < 8; nt++) {
            float d0 = acc[mt][nt][0] - muA[mt], d1 = acc[mt][nt][1] - muA[mt];
            float d2 = acc[mt][nt][2] - muB[mt], d3 = acc[mt][nt][3] - muB[mt];
            sA += d0 * d0 + d1 * d1;
            sB += d2 * d2 + d3 * d3;
        }
        sA += __shfl_xor_sync(0xFFFFFFFFu, sA, 1);
        sA += __shfl_xor_sync(0xFFFFFFFFu, sA, 2);
        sB += __shfl_xor_sync(0xFFFFFFFFu, sB, 1);
        sB += __shfl_xor_sync(0xFFFFFFFFu, sB, 2);
        if (t4 == 0) {
            red[wnid * 128 + wm + mt * 16 + gid] = sA;
            red[wnid * 128 + wm + mt * 16 + gid + 8] = sB;
        }
    }
    __syncthreads();
#pragma unroll
    for (int mt = 0; mt < 2; mt++) {
        int rA = wm + mt * 16 + gid;
        float rsA = rsqrtf((red[rA] + red[128 + rA]) * (1.f / 128.f) + EPSF);
        float rsB = rsqrtf((red[rA + 8] + red[128 + rA + 8]) * (1.f / 128.f) + EPSF);
        int nA = n0 + rA, nB = nA + 8;
#pragma unroll
        for (int nt = 0; nt < 8; nt++) {
            int col = wn + nt * 8 + t4 * 2;
            float g0 = __ldg(&gamma1[col]), g1 = __ldg(&gamma1[col + 1]);
            float be0 = __ldg(&beta1[col]), be1 = __ldg(&beta1[col + 1]);
            if (nA < NN) {
                float v0 = (acc[mt][nt][0] - muA[mt]) * rsA * g0 + be0;
                float v1 = (acc[mt][nt][1] - muA[mt]) * rsA * g1 + be1;
                size_t o = (size_t)nA * 128 + col;
                split_write2(v0, v1, g_Hh + o, g_Hl + o);
            }
            if (nB < NN) {
                float v0 = (acc[mt][nt][2] - muB[mt]) * rsB * g0 + be0;
                float v1 = (acc[mt][nt][3] - muB[mt]) * rsB * g1 + be1;
                size_t o = (size_t)nB * 128 + col;
                split_write2(v0, v1, g_Hh + o, g_Hl + o);
            }
        }
    }
}

// ================= GEMM2: C2[:, j] = H @ B2, j tiled by 128, bias2 on cols >= 512 =================
__global__ __launch_bounds__(256) void gemm2_mma(const float* __restrict__ bias2) {
    extern __shared__ char smraw[];
    char* stg[2] = { smraw, smraw + STAGE_B };

    int tid = threadIdx.x, lane = tid & 31, wid = tid >> 5;
    int n0 = blockIdx.x * 128;
    int j0 = blockIdx.y * 128;
    int wm = (wid >> 1) * 32, wn = (wid & 1) * 64;
    int gid = lane >> 2, t4 = lane & 3;

    float acc[2][8][4];
#pragma unroll
    for (int mt = 0; mt < 2; mt++)
#pragma unroll
        for (int nt = 0; nt < 8; nt++)
#pragma unroll
            for (int q = 0; q < 4; q++) acc[mt][nt][q] = 0.f;

    load_chunk<128, 128>(stg[0], n0, 0, g_Hh, g_Hl, g_B2h, g_B2l, j0, 576);
    CP_COMMIT();
#pragma unroll
    for (int c = 0; c < 2; c++) {
        if (c + 1 < 2) {
            load_chunk<128, 128>(stg[1], n0, 1, g_Hh, g_Hl, g_B2h, g_B2l, j0, 576);
            CP_COMMIT();
            CP_WAIT(1);
        } else {
            CP_WAIT(0);
        }
        __syncthreads();
        compute_chunk(stg[c & 1], wm, wn, gid, t4, acc);
        __syncthreads();
    }

#pragma unroll
    for (int mt = 0; mt < 2; mt++) {
        int nA = n0 + wm + mt * 16 + gid;
        int nB = nA + 8;
#pragma unroll
        for (int nt = 0; nt < 8; nt++) {
            int j = j0 + wn + nt * 8 + t4 * 2;
            if (j >= 576) continue;
            float b0 = 0.f, b1 = 0.f;
            if (j >= 512) { b0 = __ldg(&bias2[j - 512]); b1 = __ldg(&bias2[j - 511]); }
            if (nA < NN) {
                float2 o; o.x = acc[mt][nt][0] + b0; o.y = acc[mt][nt][1] + b1;
                *(float2*)(g_C2 + (size_t)nA * 576 + j) = o;
            }
            if (nB < NN) {
                float2 o; o.x = acc[mt][nt][2] + b0; o.y = acc[mt][nt][3] + b1;
                *(float2*)(g_C2 + (size_t)nB * 576 + j) = o;
            }
        }
    }
}

// gather2 + final LayerNorm fused: warp per dst.
__global__ void gather2_kernel(const float* __restrict__ gamma, const float* __restrict__ beta,
                               float* __restrict__ out) {
    int w = blockIdx.x * 8 + (threadIdx.x >> 5);
    if (w >= NN) return;
    int lane = threadIdx.x & 31;
    float2 acc = *(const float2*)(g_C2 + (size_t)w * 576 + 512 + lane * 2);
#pragma unroll
    for (int r = 0; r < RR; r++) {
        int seg = w * RR + r;
        int cnt = g_cnt[seg];
        if (cnt == 0) continue;
        int beg = g_off[seg];
        float inv = g_invcnt[seg];
        float sx = 0.f, sy = 0.f;
        for (int j = 0; j < cnt; j++) {
            int src = __ldg(&g_sorted[beg + j]);
            float2 v = __ldg((const float2*)(g_C2 + (size_t)src * 576 + r * 64 + lane * 2));
            sx += v.x; sy += v.y;
        }
        acc.x += sx * inv;
        acc.y += sy * inv;
    }
    float s = acc.x + acc.y;
#pragma unroll
    for (int o = 16; o; o >>= 1) s += __shfl_xor_sync(0xFFFFFFFFu, s, o);
    float mu = s * (1.f / 64.f);
    float dx = acc.x - mu, dy = acc.y - mu;
    float sq = dx * dx + dy * dy;
#pragma unroll
    for (int o = 16; o; o >>= 1) sq += __shfl_xor_sync(0xFFFFFFFFu, sq, o);
    float rstd = rsqrtf(sq * (1.f / 64.f) + EPSF);
    float2 g = ((const float2*)gamma)[lane];
    float2 b = ((const float2*)beta)[lane];
    float2 o2;
    o2.x = dx * rstd * g.x + b.x;
    o2.y = dy * rstd * g.y + b.y;
    ((float2*)out)[(size_t)w * 32 + lane] = o2;
}

// ---------------- launch ----------------
extern "C" void kernel_launch(void* const* d_in, const int* in_sizes, int n_in,
                              void* d_out, int out_size) {
    const float* x      = (const float*)d_in[0];
    const void*  ei     = d_in[1];
    const void*  et     = d_in[2];
    const float* W1     = (const float*)d_in[3];
    const float* root1  = (const float*)d_in[4];
    const float* bias1  = (const float*)d_in[5];
    const float* gamma1 = (const float*)d_in[6];
    const float* beta1  = (const float*)d_in[7];
    const float* W2     = (const float*)d_in[8];
    const float* root2  = (const float*)d_in[9];
    const float* bias2  = (const float*)d_in[10];
    const float* gamma2 = (const float*)d_in[11];
    const float* beta2  = (const float*)d_in[12];
    float* out = (float*)d_out;

    cudaFuncSetAttribute(gemm1_mma, cudaFuncAttributeMaxDynamicSharedMemorySize, GEMM_SMEM);
    cudaFuncSetAttribute(gemm2_mma, cudaFuncAttributeMaxDynamicSharedMemorySize, GEMM_SMEM);

    detect_kernel<<<1, 1>>>((const int*)ei);
    zero_cnt_kernel<<<(NSEG / 4 + 255) / 256, 256>>>();
    count_kernel<<<(EE + 255) / 256, 256>>>(ei, et);
    scan1_kernel<<<NB, 256>>>();
    scan2_kernel<<<1, 1024>>>();
    scan3_kernel<<<NB, 256>>>();
    scatter_pos_kernel<<<(EE + 255) / 256, 256>>>(ei, et);
    prep_kernel<<<(128 * 576 + 255) / 256, 256>>>(W1, root1, W2, root2);
    gather1_kernel<<<(NN + 7) / 8, 256>>>(x);
    gemm1_mma<<<(NN + 127) / 128, 256, GEMM_SMEM>>>(bias1, gamma1, beta1);
    gemm2_mma<<<dim3((NN + 127) / 128, 5), 256, GEMM_SMEM>>>(bias2);
    gather2_kernel<<<(NN + 7) / 8, 256>>>(gamma2, beta2, out);
}

// round 7
// speedup vs baseline: 1.8341x; 1.0119x over previous
#include <cuda_runtime.h>
#include <cuda_bf16.h>
#include <cstdint>

#define NN   50000
#define EE   800000
#define RR   8
#define DIN  64
#define DHID 128
#define DOUT 64
#define EPSF 1e-5f
#define NSEG (NN * RR)            // 400000
#define NB   ((NSEG + 255) / 256) // 1563 scan blocks

// ---------------- scratch (device globals; no allocation allowed) ----------------
__device__ int   g_cnt[NSEG];
__device__ int   g_off[NSEG];
__device__ int   g_cursor[NSEG];
__device__ float g_invcnt[NSEG];
__device__ int   g_sorted[EE];
__device__ int   g_bsum[NB];
__device__ int   g_bpre[NB];
__device__ float g_C2[9 * NN * DOUT];   // RELATION-MAJOR: [9][N][64]; slice 8 = root+bias
__device__ int   g_is64;

// split bf16 activations / weights (16B aligned for cp.async)
__device__ __align__(16) __nv_bfloat16 g_A1h[NN * 576];  // [N,576]: 8x64 rel means | x
__device__ __align__(16) __nv_bfloat16 g_A1l[NN * 576];
__device__ __align__(16) __nv_bfloat16 g_Hh[NN * 128];   // layer-1 output (post-LN)
__device__ __align__(16) __nv_bfloat16 g_Hl[NN * 128];
__device__ __align__(16) __nv_bfloat16 g_B1h[128 * 576]; // [Ncols,K]
__device__ __align__(16) __nv_bfloat16 g_B1l[128 * 576];
__device__ __align__(16) __nv_bfloat16 g_B2h[576 * 128];
__device__ __align__(16) __nv_bfloat16 g_B2l[576 * 128];

// ---------------- generic helpers ----------------
__device__ __forceinline__ int ld_idx(const void* p, int i, int is64) {
    if (is64) return (int)(((const long long*)p)[i]);
    return ((const int*)p)[i];
}

// zero cnt + detect edge dtype in one kernel
__global__ void init_kernel(const int* __restrict__ ei) {
    int i = blockIdx.x * 256 + threadIdx.x;
    if (i < NSEG / 4) ((int4*)g_cnt)[i] = make_int4(0, 0, 0, 0);
    if (blockIdx.x == 0 && threadIdx.x == 0) {
        int all0 = 1;
        for (int k = 0; k < 32; k++)
            if (ei[2 * k + 1] != 0) all0 = 0;
        g_is64 = all0;
    }
}

__global__ void count_kernel(const void* __restrict__ ei, const void* __restrict__ et) {
    int e = blockIdx.x * 256 + threadIdx.x;
    if (e >= EE) return;
    int is64 = g_is64;
    int dst = ld_idx(ei, EE + e, is64);
    int r   = ld_idx(et, e, is64);
    atomicAdd(&g_cnt[dst * RR + r], 1);
}

__global__ void scan1_kernel() {
    __shared__ int sm[256];
    int b = blockIdx.x, t = threadIdx.x;
    int i = b * 256 + t;
    int v = (i < NSEG) ? g_cnt[i] : 0;
    sm[t] = v;
    __syncthreads();
    for (int o = 1; o < 256; o <<= 1) {
        int u = (t >= o) ? sm[t - o] : 0;
        __syncthreads();
        sm[t] += u;
        __syncthreads();
    }
    if (i < NSEG) g_off[i] = sm[t] - v;
    if (t == 255) g_bsum[b] = sm[255];
}

__global__ void scan2_kernel() {
    __shared__ int sm[1024];
    int t = threadIdx.x;
    int i0 = 2 * t, i1 = 2 * t + 1;
    int v0 = (i0 < NB) ? g_bsum[i0] : 0;
    int v1 = (i1 < NB) ? g_bsum[i1] : 0;
    int s = v0 + v1;
    sm[t] = s;
    __syncthreads();
    for (int o = 1; o < 1024; o <<= 1) {
        int u = (t >= o) ? sm[t - o] : 0;
        __syncthreads();
        sm[t] += u;
        __syncthreads();
    }
    int e = sm[t] - s;
    if (i0 < NB) g_bpre[i0] = e;
    if (i1 < NB) g_bpre[i1] = e + v0;
}

__global__ void scan3_kernel() {
    int i = blockIdx.x * 256 + threadIdx.x;
    if (i >= NSEG) return;
    int o = g_off[i] + g_bpre[blockIdx.x];
    g_off[i] = o;
    g_cursor[i] = o;
    int c = g_cnt[i];
    g_invcnt[i] = (c > 0) ? (1.0f / (float)c) : 0.0f;
}

__global__ void scatter_pos_kernel(const void* __restrict__ ei, const void* __restrict__ et) {
    int e = blockIdx.x * 256 + threadIdx.x;
    if (e >= EE) return;
    int is64 = g_is64;
    int src = ld_idx(ei, e, is64);
    int dst = ld_idx(ei, EE + e, is64);
    int r   = ld_idx(et, e, is64);
    int pos = atomicAdd(&g_cursor[dst * RR + r], 1);
    g_sorted[pos] = src;
}

__device__ __forceinline__ void split_write2(float a, float b,
                                             __nv_bfloat16* ph, __nv_bfloat16* pl) {
    __nv_bfloat162 h = __floats2bfloat162_rn(a, b);
    *(__nv_bfloat162*)ph = h;
    __nv_bfloat162 l = __floats2bfloat162_rn(a - __bfloat162float(h.x),
                                             b - __bfloat162float(h.y));
    *(__nv_bfloat162*)pl = l;
}

// gather1: warp per dst; A1[dst, r*64:...] = split(mean x[src]); cols 512.. = split(x[dst]).
// metadata via lane-parallel load + shfl; edge loop unrolled x4 for MLP.
__global__ void gather1_kernel(const float* __restrict__ x) {
    int w = blockIdx.x * 8 + (threadIdx.x >> 5);
    if (w >= NN) return;
    int lane = threadIdx.x & 31;
    int moff = 0, mcnt = 0; float minv = 0.f;
    if (lane < 8) {
        int seg = w * RR + lane;
        moff = g_off[seg]; mcnt = g_cnt[seg]; minv = g_invcnt[seg];
    }
#pragma unroll
    for (int r = 0; r < RR; r++) {
        int beg = __shfl_sync(0xFFFFFFFFu, moff, r);
        int cnt = __shfl_sync(0xFFFFFFFFu, mcnt, r);
        float inv = __shfl_sync(0xFFFFFFFFu, minv, r);
        float sx = 0.f, sy = 0.f;
        int j = 0;
        for (; j + 4 <= cnt; j += 4) {
            int s0 = __ldg(&g_sorted[beg + j + 0]);
            int s1 = __ldg(&g_sorted[beg + j + 1]);
            int s2 = __ldg(&g_sorted[beg + j + 2]);
            int s3 = __ldg(&g_sorted[beg + j + 3]);
            float2 v0 = __ldg((const float2*)(x + (size_t)s0 * DIN + lane * 2));
            float2 v1 = __ldg((const float2*)(x + (size_t)s1 * DIN + lane * 2));
            float2 v2 = __ldg((const float2*)(x + (size_t)s2 * DIN + lane * 2));
            float2 v3 = __ldg((const float2*)(x + (size_t)s3 * DIN + lane * 2));
            sx += (v0.x + v1.x) + (v2.x + v3.x);
            sy += (v0.y + v1.y) + (v2.y + v3.y);
        }
        for (; j < cnt; j++) {
            int s0 = __ldg(&g_sorted[beg + j]);
            float2 v0 = __ldg((const float2*)(x + (size_t)s0 * DIN + lane * 2));
            sx += v0.x; sy += v0.y;
        }
        size_t o = (size_t)w * 576 + r * 64 + lane * 2;
        split_write2(sx * inv, sy * inv, g_A1h + o, g_A1l + o);
    }
    float2 xv = *(const float2*)(x + (size_t)w * 64 + lane * 2);
    size_t o = (size_t)w * 576 + 512 + lane * 2;
    split_write2(xv.x, xv.y, g_A1h + o, g_A1l + o);
}

// prep: split + transpose weights to bf16 hi/lo, [Ncols, K]
__global__ void prep_kernel(const float* __restrict__ W1, const float* __restrict__ root1,
                            const float* __restrict__ W2, const float* __restrict__ root2) {
    int idx = blockIdx.x * 256 + threadIdx.x;
    if (idx < 128 * 576) {
        int n = idx / 576, k = idx % 576;
        float v = (k < 512) ? W1[(size_t)k * 128 + n] : root1[(size_t)(k - 512) * 128 + n];
        __nv_bfloat16 h = __float2bfloat16(v);
        g_B1h[idx] = h;
        g_B1l[idx] = __float2bfloat16(v - __bfloat162float(h));
    }
    if (idx < 576 * 128) {
        int j = idx / 128, k = idx % 128;
        int r = j >> 6, col = j & 63;
        float v = (r < 8) ? W2[((size_t)r * 128 + k) * 64 + col] : root2[(size_t)k * 64 + col];
        __nv_bfloat16 h = __float2bfloat16(v);
        g_B2h[idx] = h;
        g_B2l[idx] = __float2bfloat16(v - __bfloat162float(h));
    }
}

// ---------------- mma.sync / cp.async helpers ----------------
__device__ __forceinline__ void mma_bf16(float* c, uint32_t a0, uint32_t a1, uint32_t a2,
                                         uint32_t a3, uint32_t b0, uint32_t b1) {
    asm volatile(
        "mma.sync.aligned.m16n8k16.row.col.f32.bf16.bf16.f32 "
        "{%0,%1,%2,%3}, {%4,%5,%6,%7}, {%8,%9}, {%0,%1,%2,%3};"
        : "+f"(c[0]), "+f"(c[1]), "+f"(c[2]), "+f"(c[3])
        : "r"(a0), "r"(a1), "r"(a2), "r"(a3), "r"(b0), "r"(b1));
}

__device__ __forceinline__ uint32_t smem_u32(const void* p) {
    uint32_t a;
    asm("{ .reg .u64 t; cvta.to.shared.u64 t, %1; cvt.u32.u64 %0, t; }" : "=r"(a) : "l"(p));
    return a;
}

__device__ __forceinline__ void cp16z(uint32_t dst, const void* src, bool pred) {
    int sz = pred ? 16 : 0;
    asm volatile("cp.async.ca.shared.global [%0], [%1], 16, %2;"
                 :: "r"(dst), "l"(__cvta_generic_to_global(src)), "r"(sz) : "memory");
}
#define CP_COMMIT() asm volatile("cp.async.commit_group;" ::: "memory")
#define CP_WAIT(N)  asm volatile("cp.async.wait_group %0;" :: "n"(N) : "memory")

// SMEM tile: 4 planes (Ah, Al, Bh, Bl), each [128 rows][72 bf16] (144B stride)
#define LDT 72
#define PLANE_B (128 * LDT * 2)              // bytes per plane
#define STAGE_B (4 * PLANE_B)                // 73728 bytes
#define GEMM_SMEM (2 * STAGE_B + 2 * 128 * 4)

template <int KA, int KB>
__device__ __forceinline__ void load_chunk(char* stage, int n0, int c,
                                           const __nv_bfloat16* A1h, const __nv_bfloat16* A1l,
                                           const __nv_bfloat16* B1h, const __nv_bfloat16* B1l,
                                           int brow0, int bmax) {
#pragma unroll
    for (int i = 0; i < 16; i++) {
        int l = threadIdx.x + i * 256;       // 0..4095
        int plane = l >> 10, rem = l & 1023;
        int row = rem >> 3, seg = rem & 7;
        uint32_t dst = smem_u32(stage + plane * PLANE_B + row * (LDT * 2) + seg * 16);
        if (plane < 2) {
            int n = n0 + row;
            bool v = n < NN;
            const __nv_bfloat16* s = (plane == 0 ? A1h : A1l) +
                                     (size_t)(v ? n : 0) * KA + c * 64 + seg * 8;
            cp16z(dst, s, v);
        } else {
            int j = brow0 + row;
            bool v = j < bmax;
            const __nv_bfloat16* s = (plane == 2 ? B1h : B1l) +
                                     (size_t)(v ? j : 0) * KB + c * 64 + seg * 8;
            cp16z(dst, s, v);
        }
    }
}

__device__ __forceinline__ void compute_chunk(const char* stage, int wm, int wn,
                                              int gid, int t4, float acc[2][8][4]) {
    const __nv_bfloat16* Ah = (const __nv_bfloat16*)stage;
    const __nv_bfloat16* Al = (const __nv_bfloat16*)(stage + PLANE_B);
    const __nv_bfloat16* Bh = (const __nv_bfloat16*)(stage + 2 * PLANE_B);
    const __nv_bfloat16* Bl = (const __nv_bfloat16*)(stage + 3 * PLANE_B);
#pragma unroll
    for (int ks = 0; ks < 4; ks++) {
        int kb = ks * 16 + t4 * 2;
        uint32_t Afh[2][4], Afl[2][4];
#pragma unroll
        for (int mt = 0; mt < 2; mt++) {
            const __nv_bfloat16* pa = Ah + (wm + mt * 16 + gid) * LDT;
            const __nv_bfloat16* pl = Al + (wm + mt * 16 + gid) * LDT;
            Afh[mt][0] = *(const uint32_t*)(pa + kb);
            Afh[mt][1] = *(const uint32_t*)(pa + 8 * LDT + kb);
            Afh[mt][2] = *(const uint32_t*)(pa + kb + 8);
            Afh[mt][3] = *(const uint32_t*)(pa + 8 * LDT + kb + 8);
            Afl[mt][0] = *(const uint32_t*)(pl + kb);
            Afl[mt][1] = *(const uint32_t*)(pl + 8 * LDT + kb);
            Afl[mt][2] = *(const uint32_t*)(pl + kb + 8);
            Afl[mt][3] = *(const uint32_t*)(pl + 8 * LDT + kb + 8);
        }
#pragma unroll
        for (int nt = 0; nt < 8; nt++) {
            const __nv_bfloat16* pb = Bh + (wn + nt * 8 + gid) * LDT + kb;
            const __nv_bfloat16* pbl = Bl + (wn + nt * 8 + gid) * LDT + kb;
            uint32_t bh0 = *(const uint32_t*)pb, bh1 = *(const uint32_t*)(pb + 8);
            uint32_t bl0 = *(const uint32_t*)pbl, bl1 = *(const uint32_t*)(pbl + 8);
#pragma unroll
            for (int mt = 0; mt < 2; mt++) {
                mma_bf16(acc[mt][nt], Afh[mt][0], Afh[mt][1], Afh[mt][2], Afh[mt][3], bh0, bh1);
                mma_bf16(acc[mt][nt], Afh[mt][0], Afh[mt][1], Afh[mt][2], Afh[mt][3], bl0, bl1);
                mma_bf16(acc[mt][nt], Afl[mt][0], Afl[mt][1], Afl[mt][2], Afl[mt][3], bh0, bh1);
            }
        }
    }
}

// ================= GEMM1: h = LN(leaky(A1 @ B1 + bias1)), split-bf16 output =================
__global__ __launch_bounds__(256) void gemm1_mma(
    const float* __restrict__ bias1,
    const float* __restrict__ gamma1, const float* __restrict__ beta1) {
    extern __shared__ char smraw[];
    char* stg[2] = { smraw, smraw + STAGE_B };
    float* red = (float*)(smraw + 2 * STAGE_B);  // [2][128]

    int tid = threadIdx.x, lane = tid & 31, wid = tid >> 5;
    int n0 = blockIdx.x * 128;
    int wm = (wid >> 1) * 32, wn = (wid & 1) * 64;
    int gid = lane >> 2, t4 = lane & 3;

    float acc[2][8][4];
#pragma unroll
    for (int mt = 0; mt < 2; mt++)
#pragma unroll
        for (int nt = 0; nt < 8; nt++)
#pragma unroll
            for (int q = 0; q < 4; q++) acc[mt][nt][q] = 0.f;

    load_chunk<576, 576>(stg[0], n0, 0, g_A1h, g_A1l, g_B1h, g_B1l, 0, 128);
    CP_COMMIT();
    for (int c = 0; c < 9; c++) {
        if (c + 1 < 9) {
            load_chunk<576, 576>(stg[(c + 1) & 1], n0, c + 1, g_A1h, g_A1l, g_B1h, g_B1l, 0, 128);
            CP_COMMIT();
            CP_WAIT(1);
        } else {
            CP_WAIT(0);
        }
        __syncthreads();
        compute_chunk(stg[c & 1], wm, wn, gid, t4, acc);
        __syncthreads();
    }

    // ---- epilogue: bias + leaky + LN ----
#pragma unroll
    for (int nt = 0; nt < 8; nt++) {
        int col = wn + nt * 8 + t4 * 2;
        float b0 = __ldg(&bias1[col]), b1 = __ldg(&bias1[col + 1]);
#pragma unroll
        for (int mt = 0; mt < 2; mt++) {
            float* cc = acc[mt][nt];
            cc[0] += b0; cc[1] += b1; cc[2] += b0; cc[3] += b1;
#pragma unroll
            for (int q = 0; q < 4; q++) cc[q] = (cc[q] >= 0.f) ? cc[q] : 0.2f * cc[q];
        }
    }
    int wnid = wid & 1;
#pragma unroll
    for (int mt = 0; mt < 2; mt++) {
        float sA = 0.f, sB = 0.f;
#pragma unroll
        for (int nt = 0; nt < 8; nt++) {
            sA += acc[mt][nt][0] + acc[mt][nt][1];
            sB += acc[mt][nt][2] + acc[mt][nt][3];
        }
        sA += __shfl_xor_sync(0xFFFFFFFFu, sA, 1);
        sA += __shfl_xor_sync(0xFFFFFFFFu, sA, 2);
        sB += __shfl_xor_sync(0xFFFFFFFFu, sB, 1);
        sB += __shfl_xor_sync(0xFFFFFFFFu, sB, 2);
        if (t4 == 0) {
            red[wnid * 128 + wm + mt * 16 + gid] = sA;
            red[wnid * 128 + wm + mt * 16 + gid + 8] = sB;
        }
    }
    __syncthreads();
    float muA[2], muB[2];
#pragma unroll
    for (int mt = 0; mt < 2; mt++) {
        int rA = wm + mt * 16 + gid;
        muA[mt] = (red[rA] + red[128 + rA]) * (1.f / 128.f);
        muB[mt] = (red[rA + 8] + red[128 + rA + 8]) * (1.f / 128.f);
    }
    __syncthreads();
#pragma unroll
    for (int mt = 0; mt < 2; mt++) {
        float sA = 0.f, sB = 0.f;
#pragma unroll
        for (int nt = 0; nt < 8; nt++) {
            float d0 = acc[mt][nt][0] - muA[mt], d1 = acc[mt][nt][1] - muA[mt];
            float d2 = acc[mt][nt][2] - muB[mt], d3 = acc[mt][nt][3] - muB[mt];
            sA += d0 * d0 + d1 * d1;
            sB += d2 * d2 + d3 * d3;
        }
        sA += __shfl_xor_sync(0xFFFFFFFFu, sA, 1);
        sA += __shfl_xor_sync(0xFFFFFFFFu, sA, 2);
        sB += __shfl_xor_sync(0xFFFFFFFFu, sB, 1);
        sB += __shfl_xor_sync(0xFFFFFFFFu, sB, 2);
        if (t4 == 0) {
            red[wnid * 128 + wm + mt * 16 + gid] = sA;
            red[wnid * 128 + wm + mt * 16 + gid + 8] = sB;
        }
    }
    __syncthreads();
#pragma unroll
    for (int mt = 0; mt < 2; mt++) {
        int rA = wm + mt * 16 + gid;
        float rsA = rsqrtf((red[rA] + red[128 + rA]) * (1.f / 128.f) + EPSF);
        float rsB = rsqrtf((red[rA + 8] + red[128 + rA + 8]) * (1.f / 128.f) + EPSF);
        int nA = n0 + rA, nB = nA + 8;
#pragma unroll
        for (int nt = 0; nt < 8; nt++) {
            int col = wn + nt * 8 + t4 * 2;
            float g0 = __ldg(&gamma1[col]), g1 = __ldg(&gamma1[col + 1]);
            float be0 = __ldg(&beta1[col]), be1 = __ldg(&beta1[col + 1]);
            if (nA < NN) {
                float v0 = (acc[mt][nt][0] - muA[mt]) * rsA * g0 + be0;
                float v1 = (acc[mt][nt][1] - muA[mt]) * rsA * g1 + be1;
                size_t o = (size_t)nA * 128 + col;
                split_write2(v0, v1, g_Hh + o, g_Hl + o);
            }
            if (nB < NN) {
                float v0 = (acc[mt][nt][2] - muB[mt]) * rsB * g0 + be0;
                float v1 = (acc[mt][nt][3] - muB[mt]) * rsB * g1 + be1;
                size_t o = (size_t)nB * 128 + col;
                split_write2(v0, v1, g_Hh + o, g_Hl + o);
            }
        }
    }
}

// ============ GEMM2: C2[r][n][c] (relation-major) = H @ B2, bias2 on slice 8 ============
__global__ __launch_bounds__(256) void gemm2_mma(const float* __restrict__ bias2) {
    extern __shared__ char smraw[];
    char* stg[2] = { smraw, smraw + STAGE_B };

    int tid = threadIdx.x, lane = tid & 31, wid = tid >> 5;
    int n0 = blockIdx.x * 128;
    int j0 = blockIdx.y * 128;
    int wm = (wid >> 1) * 32, wn = (wid & 1) * 64;
    int gid = lane >> 2, t4 = lane & 3;

    float acc[2][8][4];
#pragma unroll
    for (int mt = 0; mt < 2; mt++)
#pragma unroll
        for (int nt = 0; nt < 8; nt++)
#pragma unroll
            for (int q = 0; q < 4; q++) acc[mt][nt][q] = 0.f;

    load_chunk<128, 128>(stg[0], n0, 0, g_Hh, g_Hl, g_B2h, g_B2l, j0, 576);
    CP_COMMIT();
#pragma unroll
    for (int c = 0; c < 2; c++) {
        if (c + 1 < 2) {
            load_chunk<128, 128>(stg[1], n0, 1, g_Hh, g_Hl, g_B2h, g_B2l, j0, 576);
            CP_COMMIT();
            CP_WAIT(1);
        } else {
            CP_WAIT(0);
        }
        __syncthreads();
        compute_chunk(stg[c & 1], wm, wn, gid, t4, acc);
        __syncthreads();
    }

#pragma unroll
    for (int mt = 0; mt < 2; mt++) {
        int nA = n0 + wm + mt * 16 + gid;
        int nB = nA + 8;
#pragma unroll
        for (int nt = 0; nt < 8; nt++) {
            int j = j0 + wn + nt * 8 + t4 * 2;
            if (j >= 576) continue;
            int r = j >> 6, cc = j & 63;
            float b0 = 0.f, b1 = 0.f;
            if (j >= 512) { b0 = __ldg(&bias2[cc]); b1 = __ldg(&bias2[cc + 1]); }
            if (nA < NN) {
                float2 o; o.x = acc[mt][nt][0] + b0; o.y = acc[mt][nt][1] + b1;
                *(float2*)(g_C2 + ((size_t)r * NN + nA) * 64 + cc) = o;
            }
            if (nB < NN) {
                float2 o; o.x = acc[mt][nt][2] + b0; o.y = acc[mt][nt][3] + b1;
                *(float2*)(g_C2 + ((size_t)r * NN + nB) * 64 + cc) = o;
            }
        }
    }
}

// gather2 + final LayerNorm fused: warp per dst; relation-major C2, x4 unrolled.
__global__ void gather2_kernel(const float* __restrict__ gamma, const float* __restrict__ beta,
                               float* __restrict__ out) {
    int w = blockIdx.x * 8 + (threadIdx.x >> 5);
    if (w >= NN) return;
    int lane = threadIdx.x & 31;
    int moff = 0, mcnt = 0; float minv = 0.f;
    if (lane < 8) {
        int seg = w * RR + lane;
        moff = g_off[seg]; mcnt = g_cnt[seg]; minv = g_invcnt[seg];
    }
    float2 acc = *(const float2*)(g_C2 + ((size_t)8 * NN + w) * 64 + lane * 2);
#pragma unroll
    for (int r = 0; r < RR; r++) {
        int beg = __shfl_sync(0xFFFFFFFFu, moff, r);
        int cnt = __shfl_sync(0xFFFFFFFFu, mcnt, r);
        if (cnt == 0) continue;
        float inv = __shfl_sync(0xFFFFFFFFu, minv, r);
        const float* slice = g_C2 + (size_t)r * NN * 64 + lane * 2;
        float sx = 0.f, sy = 0.f;
        int j = 0;
        for (; j + 4 <= cnt; j += 4) {
            int s0 = __ldg(&g_sorted[beg + j + 0]);
            int s1 = __ldg(&g_sorted[beg + j + 1]);
            int s2 = __ldg(&g_sorted[beg + j + 2]);
            int s3 = __ldg(&g_sorted[beg + j + 3]);
            float2 v0 = __ldg((const float2*)(slice + (size_t)s0 * 64));
            float2 v1 = __ldg((const float2*)(slice + (size_t)s1 * 64));
            float2 v2 = __ldg((const float2*)(slice + (size_t)s2 * 64));
            float2 v3 = __ldg((const float2*)(slice + (size_t)s3 * 64));
            sx += (v0.x + v1.x) + (v2.x + v3.x);
            sy += (v0.y + v1.y) + (v2.y + v3.y);
        }
        for (; j < cnt; j++) {
            int s0 = __ldg(&g_sorted[beg + j]);
            float2 v0 = __ldg((const float2*)(slice + (size_t)s0 * 64));
            sx += v0.x; sy += v0.y;
        }
        acc.x += sx * inv;
        acc.y += sy * inv;
    }
    float s = acc.x + acc.y;
#pragma unroll
    for (int o = 16; o; o >>= 1) s += __shfl_xor_sync(0xFFFFFFFFu, s, o);
    float mu = s * (1.f / 64.f);
    float dx = acc.x - mu, dy = acc.y - mu;
    float sq = dx * dx + dy * dy;
#pragma unroll
    for (int o = 16; o; o >>= 1) sq += __shfl_xor_sync(0xFFFFFFFFu, sq, o);
    float rstd = rsqrtf(sq * (1.f / 64.f) + EPSF);
    float2 g = ((const float2*)gamma)[lane];
    float2 b = ((const float2*)beta)[lane];
    float2 o2;
    o2.x = dx * rstd * g.x + b.x;
    o2.y = dy * rstd * g.y + b.y;
    ((float2*)out)[(size_t)w * 32 + lane] = o2;
}

// ---------------- launch ----------------
extern "C" void kernel_launch(void* const* d_in, const int* in_sizes, int n_in,
                              void* d_out, int out_size) {
    const float* x      = (const float*)d_in[0];
    const void*  ei     = d_in[1];
    const void*  et     = d_in[2];
    const float* W1     = (const float*)d_in[3];
    const float* root1  = (const float*)d_in[4];
    const float* bias1  = (const float*)d_in[5];
    const float* gamma1 = (const float*)d_in[6];
    const float* beta1  = (const float*)d_in[7];
    const float* W2     = (const float*)d_in[8];
    const float* root2  = (const float*)d_in[9];
    const float* bias2  = (const float*)d_in[10];
    const float* gamma2 = (const float*)d_in[11];
    const float* beta2  = (const float*)d_in[12];
    float* out = (float*)d_out;

    cudaFuncSetAttribute(gemm1_mma, cudaFuncAttributeMaxDynamicSharedMemorySize, GEMM_SMEM);
    cudaFuncSetAttribute(gemm2_mma, cudaFuncAttributeMaxDynamicSharedMemorySize, GEMM_SMEM);

    init_kernel<<<(NSEG / 4 + 255) / 256, 256>>>((const int*)ei);
    count_kernel<<<(EE + 255) / 256, 256>>>(ei, et);
    scan1_kernel<<<NB, 256>>>();
    scan2_kernel<<<1, 1024>>>();
    scan3_kernel<<<NB, 256>>>();
    scatter_pos_kernel<<<(EE + 255) / 256, 256>>>(ei, et);
    prep_kernel<<<(128 * 576 + 255) / 256, 256>>>(W1, root1, W2, root2);
    gather1_kernel<<<(NN + 7) / 8, 256>>>(x);
    gemm1_mma<<<(NN + 127) / 128, 256, GEMM_SMEM>>>(bias1, gamma1, beta1);
    gemm2_mma<<<dim3((NN + 127) / 128, 5), 256, GEMM_SMEM>>>(bias2);
    gather2_kernel<<<(NN + 7) / 8, 256>>>(gamma2, beta2, out);
}